// round 16
// baseline (speedup 1.0000x reference)
#include <cuda_runtime.h>
#include <cuda_bf16.h>

#define NPIX 9216
#define HW   96
#define CIN  256
#define C8   32

// ---------------- scratch: __device__ globals (no allocation allowed) ----------
__device__ __align__(128) __nv_bfloat16 g_Zt[NPIX * C8];               // Zt[q][o], q = w*96+h
__device__ __align__(128) __nv_bfloat16 g_ET[(size_t)NPIX * NPIX];     // E^T: [j][p] = exp(G[p][j])  (170MB)
__device__ __align__(128) float         g_srow[NPIX];                  // s_p = sum_j exp(G[p][j])
__device__ __align__(128) __nv_bfloat16 g_Ap[CIN * NPIX];              // A'[c][p] = x[c][p] / s_p
__device__ __align__(128) float         g_x6[(size_t)CIN * NPIX];      // logits of 2nd softmax
__device__ __align__(128) float         g_m6[CIN];
__device__ __align__(128) float         g_s6[CIN];

__device__ __forceinline__ void mma_bf16_16816(float* d, const unsigned* a,
                                               unsigned b0, unsigned b1) {
    asm volatile(
        "mma.sync.aligned.m16n8k16.row.col.f32.bf16.bf16.f32 "
        "{%0,%1,%2,%3}, {%4,%5,%6,%7}, {%8,%9}, {%0,%1,%2,%3};\n"
        : "+f"(d[0]), "+f"(d[1]), "+f"(d[2]), "+f"(d[3])
        : "r"(a[0]), "r"(a[1]), "r"(a[2]), "r"(a[3]), "r"(b0), "r"(b1));
}

// ================= K1: 1x1 conv -> Z (bf16, stored as Zt[q][32]) ==============
// grid 288 x 256 threads. Each block: 32 consecutive p_hw pixels, all 32 outputs.
__global__ __launch_bounds__(256) void k1_conv(const float* __restrict__ x,
                                               const float* __restrict__ w,
                                               const float* __restrict__ bias) {
    __shared__ float ws[C8 * CIN];   // 32KB
    int t = threadIdx.x;
    for (int i = t; i < C8 * CIN; i += 256) ws[i] = w[i];
    __syncthreads();
    int px = t & 31;         // pixel within block
    int og = t >> 5;         // output group (4 outputs each)
    int p  = blockIdx.x * 32 + px;            // p = h*96 + w
    float a0 = __ldg(&bias[og * 4 + 0]);
    float a1 = __ldg(&bias[og * 4 + 1]);
    float a2 = __ldg(&bias[og * 4 + 2]);
    float a3 = __ldg(&bias[og * 4 + 3]);
    const float* xp = x + p;
#pragma unroll 8
    for (int c = 0; c < CIN; ++c) {
        float xv = __ldg(xp + (size_t)c * NPIX);
        a0 += ws[(og * 4 + 0) * CIN + c] * xv;
        a1 += ws[(og * 4 + 1) * CIN + c] * xv;
        a2 += ws[(og * 4 + 2) * CIN + c] * xv;
        a3 += ws[(og * 4 + 3) * CIN + c] * xv;
    }
    int h = p / HW, wc = p % HW;
    int q = wc * HW + h;                      // transposed pixel index
    __nv_bfloat162 v01, v23;
    v01.x = __float2bfloat16(a0); v01.y = __float2bfloat16(a1);
    v23.x = __float2bfloat16(a2); v23.y = __float2bfloat16(a3);
    *(__nv_bfloat162*)(&g_Zt[(size_t)q * C8 + og * 4])     = v01;
    *(__nv_bfloat162*)(&g_Zt[(size_t)q * C8 + og * 4 + 2]) = v23;
}

// ================= K2: E^T = exp(Zt Zt^T)^T (bf16) + row sums =================
// CTA: 64 G-rows (p), 256 thr = 8 warps (mw = wid&3 -> 16 rows, nw = wid>>2 -> 64 cols).
// Loops 72 J-tiles of 128 cols; G via mma (K=32), exp, staged to smem, written as E^T rows.
__global__ __launch_bounds__(256) void k2_attn1() {
    __shared__ __align__(16) __nv_bfloat16 Bs[128 * 56];   // Bs[j][k], pad 56
    __shared__ __align__(16) __nv_bfloat16 Es[128 * 72];   // Es[j_local][p_local], pad 72
    __shared__ float rs2[2 * 64];                          // per-nw row sums (deterministic)
    int t = threadIdx.x, lane = t & 31, wid = t >> 5;
    int mw = wid & 3, nw = wid >> 2;
    int p0 = blockIdx.x * 64;

    for (int i = t; i < 2 * 64; i += 256) rs2[i] = 0.f;

    // A fragments: Zt rows of this CTA's p-block, kept in registers for whole kernel
    unsigned afr[2][4];
    {
        const unsigned* zt = (const unsigned*)g_Zt;
        int r0 = p0 + mw * 16 + (lane >> 2);
        int kq = lane & 3;
#pragma unroll
        for (int kf = 0; kf < 2; ++kf) {
            afr[kf][0] = zt[(size_t)r0 * 16 + kf * 8 + kq];
            afr[kf][1] = zt[(size_t)(r0 + 8) * 16 + kf * 8 + kq];
            afr[kf][2] = zt[(size_t)r0 * 16 + kf * 8 + 4 + kq];
            afr[kf][3] = zt[(size_t)(r0 + 8) * 16 + kf * 8 + 4 + kq];
        }
    }
    __syncthreads();

    int prow = mw * 16 + (lane >> 2);
    for (int jt = 0; jt < 72; ++jt) {
        int j0 = jt * 128;
        // stage Bs[j][k] = g_Zt[(j0+j)*32 + k]  (rows of 64B)
#pragma unroll
        for (int i = 0; i < 2; ++i) {
            int e = t + i * 256;
            int row = e >> 2, part = e & 3;
            uint4 v = ((const uint4*)g_Zt)[(size_t)(j0 + row) * 4 + part];
            *(uint4*)((char*)Bs + row * 112 + part * 16) = v;
        }
        __syncthreads();

        float acc[8][4];
#pragma unroll
        for (int nt = 0; nt < 8; ++nt)
            acc[nt][0] = acc[nt][1] = acc[nt][2] = acc[nt][3] = 0.f;

#pragma unroll
        for (int kf = 0; kf < 2; ++kf) {
#pragma unroll
            for (int nt = 0; nt < 8; ++nt) {
                int nl = nw * 64 + nt * 8 + (lane >> 2);
                const char* bp = (const char*)Bs + nl * 112 + (lane & 3) * 4 + kf * 32;
                unsigned b0 = *(const unsigned*)bp;
                unsigned b1 = *(const unsigned*)(bp + 16);
                mma_bf16_16816(acc[nt], afr[kf], b0, b1);
            }
        }
        // exp, stage to Es (transposed: [j][p]), accumulate row sums
        float s0 = 0.f, s1 = 0.f;
#pragma unroll
        for (int nt = 0; nt < 8; ++nt) {
            int jl = nw * 64 + nt * 8 + ((lane & 3) << 1);
            float e00 = __expf(acc[nt][0]);
            float e01 = __expf(acc[nt][1]);
            float e10 = __expf(acc[nt][2]);
            float e11 = __expf(acc[nt][3]);
            s0 += e00 + e01;  s1 += e10 + e11;
            Es[jl * 72 + prow]           = __float2bfloat16(e00);
            Es[(jl + 1) * 72 + prow]     = __float2bfloat16(e01);
            Es[jl * 72 + prow + 8]       = __float2bfloat16(e10);
            Es[(jl + 1) * 72 + prow + 8] = __float2bfloat16(e11);
        }
        s0 += __shfl_xor_sync(0xffffffffu, s0, 1);
        s0 += __shfl_xor_sync(0xffffffffu, s0, 2);
        s1 += __shfl_xor_sync(0xffffffffu, s1, 1);
        s1 += __shfl_xor_sync(0xffffffffu, s1, 2);
        if ((lane & 3) == 0) {                      // exclusive cells per warp: no atomics
            rs2[nw * 64 + prow]     += s0;
            rs2[nw * 64 + prow + 8] += s1;
        }
        __syncthreads();
        // coalesced copy-out: Es rows (128B each) -> g_ET[(j0+j)][p0..p0+63]
#pragma unroll
        for (int i = 0; i < 4; ++i) {
            int e = t + i * 256;
            int row = e >> 3, part = e & 7;
            uint4 v = *(const uint4*)((const char*)Es + row * 144 + part * 16);
            *(uint4*)((char*)g_ET + ((size_t)(j0 + row) * NPIX + p0) * 2 + part * 16) = v;
        }
        __syncthreads();
    }
    if (t < 64) g_srow[p0 + t] = rs2[t] + rs2[64 + t];
}

// ======== K2b: A'[c][p] = x[c][p] / s_p  (bf16) ========
__global__ __launch_bounds__(256) void k2b_scaleA(const float* __restrict__ x) {
    int i = blockIdx.x * 256 + threadIdx.x;
    int p = i % NPIX;
    float v = x[i] * __frcp_rn(g_srow[p]);
    g_Ap[i] = __float2bfloat16(v);
}

// ================= K3: x6 logits = A' @ E  (bf16 mma, fp32 accum) =============
// grid (72, 2): CTA tile 128x128, K=9216 in chunks of 32.
// Double-buffered smem (pitch 40 elems = 80B, conflict-free fragment reads),
// one __syncthreads per chunk; next-chunk LDGs issue before the MMA block.
#define K3P 40   // smem pitch in bf16 elems (80 bytes)
__global__ __launch_bounds__(256, 1) void k3_gemm2() {
    __shared__ __align__(16) __nv_bfloat16 As[2][128 * K3P];
    __shared__ __align__(16) __nv_bfloat16 Bsm[2][128 * K3P];
    int t = threadIdx.x, lane = t & 31, wid = t >> 5;
    int mw = wid & 3, nw = wid >> 2;
    int m0 = blockIdx.y * 128;
    int j0 = blockIdx.x * 128;

    float acc[2][8][4];
#pragma unroll
    for (int mt = 0; mt < 2; ++mt)
#pragma unroll
        for (int nt = 0; nt < 8; ++nt)
            acc[mt][nt][0] = acc[mt][nt][1] = acc[mt][nt][2] = acc[mt][nt][3] = 0.f;

    int rowa = t >> 2, parta = t & 3;       // staging coords (each thread: 2 rows)
    uint4 va[2], vb[2];
    // ---- prologue: load + stage chunk 0 into buffer 0 ----
#pragma unroll
    for (int i = 0; i < 2; ++i) {
        int row = rowa + i * 64;
        va[i] = *(const uint4*)((const char*)g_Ap + ((size_t)(m0 + row) * NPIX) * 2 + parta * 16);
        vb[i] = *(const uint4*)((const char*)g_ET + ((size_t)(j0 + row) * NPIX) * 2 + parta * 16);
    }
#pragma unroll
    for (int i = 0; i < 2; ++i) {
        int row = rowa + i * 64;
        *(uint4*)((char*)As[0]  + row * (K3P * 2) + parta * 16) = va[i];
        *(uint4*)((char*)Bsm[0] + row * (K3P * 2) + parta * 16) = vb[i];
    }
    __syncthreads();

    const int NK = NPIX / 32;   // 288
    for (int kc = 0; kc < NK; ++kc) {
        int cur = kc & 1;
        if (kc + 1 < NK) {      // issue next-chunk LDGs (latency hidden by MMAs below)
            size_t koff = (size_t)(kc + 1) * 32;
#pragma unroll
            for (int i = 0; i < 2; ++i) {
                int row = rowa + i * 64;
                va[i] = *(const uint4*)((const char*)g_Ap +
                        ((size_t)(m0 + row) * NPIX + koff) * 2 + parta * 16);
                vb[i] = *(const uint4*)((const char*)g_ET +
                        ((size_t)(j0 + row) * NPIX + koff) * 2 + parta * 16);
            }
        }
        // ---- MMA on buffer `cur` ----
#pragma unroll
        for (int kf = 0; kf < 2; ++kf) {
            unsigned af[2][4];
#pragma unroll
            for (int mt = 0; mt < 2; ++mt) {
                int ml = mw * 32 + mt * 16 + (lane >> 2);
                const char* ap = (const char*)As[cur] + ml * (K3P * 2) + (lane & 3) * 4 + kf * 32;
                af[mt][0] = *(const unsigned*)ap;
                af[mt][1] = *(const unsigned*)(ap + 8 * (K3P * 2));
                af[mt][2] = *(const unsigned*)(ap + 16);
                af[mt][3] = *(const unsigned*)(ap + 8 * (K3P * 2) + 16);
            }
#pragma unroll
            for (int nt = 0; nt < 8; ++nt) {
                int nl = nw * 64 + nt * 8 + (lane >> 2);
                const char* bp = (const char*)Bsm[cur] + nl * (K3P * 2) + (lane & 3) * 4 + kf * 32;
                unsigned b0 = *(const unsigned*)bp;
                unsigned b1 = *(const unsigned*)(bp + 16);
                mma_bf16_16816(acc[0][nt], af[0], b0, b1);
                mma_bf16_16816(acc[1][nt], af[1], b0, b1);
            }
        }
        // ---- stage next chunk into the other buffer ----
        if (kc + 1 < NK) {
#pragma unroll
            for (int i = 0; i < 2; ++i) {
                int row = rowa + i * 64;
                *(uint4*)((char*)As[cur ^ 1]  + row * (K3P * 2) + parta * 16) = va[i];
                *(uint4*)((char*)Bsm[cur ^ 1] + row * (K3P * 2) + parta * 16) = vb[i];
            }
        }
        __syncthreads();
    }
    // epilogue: fp32 logits
#pragma unroll
    for (int mt = 0; mt < 2; ++mt) {
        int m = m0 + mw * 32 + mt * 16 + (lane >> 2);
#pragma unroll
        for (int nt = 0; nt < 8; ++nt) {
            int j = j0 + nw * 64 + nt * 8 + ((lane & 3) << 1);
            *(float2*)&g_x6[(size_t)m * NPIX + j]       = make_float2(acc[mt][nt][0], acc[mt][nt][1]);
            *(float2*)&g_x6[(size_t)(m + 8) * NPIX + j] = make_float2(acc[mt][nt][2], acc[mt][nt][3]);
        }
    }
}

// ======== K4: per-row (c) max & sumexp of x6 logits ========
__global__ __launch_bounds__(256) void k4_rowstats() {
    __shared__ float sm[256];
    int c = blockIdx.x, t = threadIdx.x;
    const float* row = g_x6 + (size_t)c * NPIX;
    float m = -3.0e38f;
    for (int i = t; i < NPIX; i += 256) m = fmaxf(m, row[i]);
    sm[t] = m;
    __syncthreads();
    for (int s = 128; s > 0; s >>= 1) {
        if (t < s) sm[t] = fmaxf(sm[t], sm[t + s]);
        __syncthreads();
    }
    m = sm[0];
    __syncthreads();
    float acc = 0.f;
    for (int i = t; i < NPIX; i += 256) acc += __expf(row[i] - m);
    sm[t] = acc;
    __syncthreads();
    for (int s = 128; s > 0; s >>= 1) {
        if (t < s) sm[t] += sm[t + s];
        __syncthreads();
    }
    if (t == 0) { g_m6[c] = m; g_s6[c] = sm[0]; }
}

// ======== K5: out = softmax_w( softmax(x6)[c,h*96+w] + x[c,h,w] ) ========
// one warp per (c,h) row of 96; grid 3072 x 256
__global__ __launch_bounds__(256) void k5_final(const float* __restrict__ x,
                                                float* __restrict__ out) {
    int gw   = blockIdx.x * 8 + (threadIdx.x >> 5);
    int lane = threadIdx.x & 31;
    int c = gw / HW, h = gw % HW;
    float m6  = g_m6[c];
    float is6 = __frcp_rn(g_s6[c]);
    float v[3];
    size_t base = (size_t)c * NPIX + h * HW;
#pragma unroll
    for (int k = 0; k < 3; ++k) {
        size_t idx = base + lane + 32 * k;
        float x6 = __expf(g_x6[idx] - m6) * is6;
        v[k] = x6 + x[idx];
    }
    float mx = fmaxf(fmaxf(v[0], v[1]), v[2]);
#pragma unroll
    for (int o = 16; o > 0; o >>= 1) mx = fmaxf(mx, __shfl_xor_sync(0xffffffffu, mx, o));
    float e[3];
    float s = 0.f;
#pragma unroll
    for (int k = 0; k < 3; ++k) { e[k] = __expf(v[k] - mx); s += e[k]; }
#pragma unroll
    for (int o = 16; o > 0; o >>= 1) s += __shfl_xor_sync(0xffffffffu, s, o);
    float is = __frcp_rn(s);
#pragma unroll
    for (int k = 0; k < 3; ++k) out[base + lane + 32 * k] = e[k] * is;
}

// =============================== launch ======================================
extern "C" void kernel_launch(void* const* d_in, const int* in_sizes, int n_in,
                              void* d_out, int out_size) {
    const float* x = nullptr; const float* w = nullptr; const float* b = nullptr;
    for (int i = 0; i < n_in; ++i) {
        if      (in_sizes[i] == CIN * NPIX) x = (const float*)d_in[i];
        else if (in_sizes[i] == C8 * CIN)   w = (const float*)d_in[i];
        else if (in_sizes[i] == C8)         b = (const float*)d_in[i];
    }
    float* out = (float*)d_out;

    k1_conv   <<<NPIX / 32, 256>>>(x, w, b);
    k2_attn1  <<<NPIX / 64, 256>>>();
    k2b_scaleA<<<(CIN * NPIX) / 256, 256>>>(x);
    k3_gemm2  <<<dim3(NPIX / 128, CIN / 128), 256>>>();
    k4_rowstats<<<CIN, 256>>>();
    k5_final  <<<(CIN * HW) / 8, 256>>>(x, out);
}

// round 17
// speedup vs baseline: 1.1302x; 1.1302x over previous
#include <cuda_runtime.h>
#include <cuda_bf16.h>

#define NPIX 9216
#define HW   96
#define CIN  256
#define C8   32

// ---------------- scratch: __device__ globals (no allocation allowed) ----------
__device__ __align__(128) __nv_bfloat16 g_Zt[NPIX * C8];               // Zt[q][o], q = w*96+h
__device__ __align__(128) __nv_bfloat16 g_ET[(size_t)NPIX * NPIX];     // E^T: [j][p] = exp(G[p][j])  (170MB)
__device__ __align__(128) float         g_srow[NPIX];                  // s_p = sum_j exp(G[p][j])
__device__ __align__(128) __nv_bfloat16 g_Ap[CIN * NPIX];              // A'[c][p] = x[c][p] / s_p
__device__ __align__(128) float         g_x6[(size_t)CIN * NPIX];      // logits of 2nd softmax
__device__ __align__(128) float         g_m6[CIN];
__device__ __align__(128) float         g_s6[CIN];

__device__ __forceinline__ void mma_bf16_16816(float* d, const unsigned* a,
                                               unsigned b0, unsigned b1) {
    asm volatile(
        "mma.sync.aligned.m16n8k16.row.col.f32.bf16.bf16.f32 "
        "{%0,%1,%2,%3}, {%4,%5,%6,%7}, {%8,%9}, {%0,%1,%2,%3};\n"
        : "+f"(d[0]), "+f"(d[1]), "+f"(d[2]), "+f"(d[3])
        : "r"(a[0]), "r"(a[1]), "r"(a[2]), "r"(a[3]), "r"(b0), "r"(b1));
}

__device__ __forceinline__ unsigned su32(const void* p) {
    unsigned r;
    asm("{ .reg .u64 t; cvta.to.shared.u64 t, %1; cvt.u32.u64 %0, t; }"
        : "=r"(r) : "l"(p));
    return r;
}

__device__ __forceinline__ void ldsm4(unsigned& r0, unsigned& r1, unsigned& r2,
                                      unsigned& r3, unsigned addr) {
    asm volatile("ldmatrix.sync.aligned.m8n8.x4.shared.b16 {%0,%1,%2,%3}, [%4];\n"
        : "=r"(r0), "=r"(r1), "=r"(r2), "=r"(r3) : "r"(addr));
}

#define CP16(dst, src) \
    asm volatile("cp.async.cg.shared.global [%0], [%1], 16;\n" :: "r"(dst), "l"(src))
#define CP_COMMIT() asm volatile("cp.async.commit_group;\n" ::: "memory")
#define CP_WAIT1()  asm volatile("cp.async.wait_group 1;\n" ::: "memory")
#define CP_WAIT0()  asm volatile("cp.async.wait_group 0;\n" ::: "memory")

// ================= K1: 1x1 conv -> Z (bf16, stored as Zt[q][32]) ==============
// grid 288 x 256 threads. Each block: 32 consecutive p_hw pixels, all 32 outputs.
__global__ __launch_bounds__(256) void k1_conv(const float* __restrict__ x,
                                               const float* __restrict__ w,
                                               const float* __restrict__ bias) {
    __shared__ float ws[C8 * CIN];   // 32KB
    int t = threadIdx.x;
    for (int i = t; i < C8 * CIN; i += 256) ws[i] = w[i];
    __syncthreads();
    int px = t & 31;         // pixel within block
    int og = t >> 5;         // output group (4 outputs each)
    int p  = blockIdx.x * 32 + px;            // p = h*96 + w
    float a0 = __ldg(&bias[og * 4 + 0]);
    float a1 = __ldg(&bias[og * 4 + 1]);
    float a2 = __ldg(&bias[og * 4 + 2]);
    float a3 = __ldg(&bias[og * 4 + 3]);
    const float* xp = x + p;
#pragma unroll 8
    for (int c = 0; c < CIN; ++c) {
        float xv = __ldg(xp + (size_t)c * NPIX);
        a0 += ws[(og * 4 + 0) * CIN + c] * xv;
        a1 += ws[(og * 4 + 1) * CIN + c] * xv;
        a2 += ws[(og * 4 + 2) * CIN + c] * xv;
        a3 += ws[(og * 4 + 3) * CIN + c] * xv;
    }
    int h = p / HW, wc = p % HW;
    int q = wc * HW + h;                      // transposed pixel index
    __nv_bfloat162 v01, v23;
    v01.x = __float2bfloat16(a0); v01.y = __float2bfloat16(a1);
    v23.x = __float2bfloat16(a2); v23.y = __float2bfloat16(a3);
    *(__nv_bfloat162*)(&g_Zt[(size_t)q * C8 + og * 4])     = v01;
    *(__nv_bfloat162*)(&g_Zt[(size_t)q * C8 + og * 4 + 2]) = v23;
}

// ================= K2: E^T = exp(Zt Zt^T)^T (bf16) + row sums =================
// CTA: 64 G-rows (p), 256 thr = 8 warps (mw = wid&3 -> 16 rows, nw = wid>>2 -> 64 cols).
// Loops 72 J-tiles of 128 cols; G via mma (K=32), exp, staged to smem, written as E^T rows.
__global__ __launch_bounds__(256) void k2_attn1() {
    __shared__ __align__(16) __nv_bfloat16 Bs[128 * 56];   // Bs[j][k], pad 56
    __shared__ __align__(16) __nv_bfloat16 Es[128 * 72];   // Es[j_local][p_local], pad 72
    __shared__ float rs2[2 * 64];                          // per-nw row sums (deterministic)
    int t = threadIdx.x, lane = t & 31, wid = t >> 5;
    int mw = wid & 3, nw = wid >> 2;
    int p0 = blockIdx.x * 64;

    for (int i = t; i < 2 * 64; i += 256) rs2[i] = 0.f;

    // A fragments: Zt rows of this CTA's p-block, kept in registers for whole kernel
    unsigned afr[2][4];
    {
        const unsigned* zt = (const unsigned*)g_Zt;
        int r0 = p0 + mw * 16 + (lane >> 2);
        int kq = lane & 3;
#pragma unroll
        for (int kf = 0; kf < 2; ++kf) {
            afr[kf][0] = zt[(size_t)r0 * 16 + kf * 8 + kq];
            afr[kf][1] = zt[(size_t)(r0 + 8) * 16 + kf * 8 + kq];
            afr[kf][2] = zt[(size_t)r0 * 16 + kf * 8 + 4 + kq];
            afr[kf][3] = zt[(size_t)(r0 + 8) * 16 + kf * 8 + 4 + kq];
        }
    }
    __syncthreads();

    int prow = mw * 16 + (lane >> 2);
    for (int jt = 0; jt < 72; ++jt) {
        int j0 = jt * 128;
        // stage Bs[j][k] = g_Zt[(j0+j)*32 + k]  (rows of 64B)
#pragma unroll
        for (int i = 0; i < 2; ++i) {
            int e = t + i * 256;
            int row = e >> 2, part = e & 3;
            uint4 v = ((const uint4*)g_Zt)[(size_t)(j0 + row) * 4 + part];
            *(uint4*)((char*)Bs + row * 112 + part * 16) = v;
        }
        __syncthreads();

        float acc[8][4];
#pragma unroll
        for (int nt = 0; nt < 8; ++nt)
            acc[nt][0] = acc[nt][1] = acc[nt][2] = acc[nt][3] = 0.f;

#pragma unroll
        for (int kf = 0; kf < 2; ++kf) {
#pragma unroll
            for (int nt = 0; nt < 8; ++nt) {
                int nl = nw * 64 + nt * 8 + (lane >> 2);
                const char* bp = (const char*)Bs + nl * 112 + (lane & 3) * 4 + kf * 32;
                unsigned b0 = *(const unsigned*)bp;
                unsigned b1 = *(const unsigned*)(bp + 16);
                mma_bf16_16816(acc[nt], afr[kf], b0, b1);
            }
        }
        // exp, stage to Es (transposed: [j][p]), accumulate row sums
        float s0 = 0.f, s1 = 0.f;
#pragma unroll
        for (int nt = 0; nt < 8; ++nt) {
            int jl = nw * 64 + nt * 8 + ((lane & 3) << 1);
            float e00 = __expf(acc[nt][0]);
            float e01 = __expf(acc[nt][1]);
            float e10 = __expf(acc[nt][2]);
            float e11 = __expf(acc[nt][3]);
            s0 += e00 + e01;  s1 += e10 + e11;
            Es[jl * 72 + prow]           = __float2bfloat16(e00);
            Es[(jl + 1) * 72 + prow]     = __float2bfloat16(e01);
            Es[jl * 72 + prow + 8]       = __float2bfloat16(e10);
            Es[(jl + 1) * 72 + prow + 8] = __float2bfloat16(e11);
        }
        s0 += __shfl_xor_sync(0xffffffffu, s0, 1);
        s0 += __shfl_xor_sync(0xffffffffu, s0, 2);
        s1 += __shfl_xor_sync(0xffffffffu, s1, 1);
        s1 += __shfl_xor_sync(0xffffffffu, s1, 2);
        if ((lane & 3) == 0) {                      // exclusive cells per warp: no atomics
            rs2[nw * 64 + prow]     += s0;
            rs2[nw * 64 + prow + 8] += s1;
        }
        __syncthreads();
        // coalesced copy-out: Es rows (128B each) -> g_ET[(j0+j)][p0..p0+63]
#pragma unroll
        for (int i = 0; i < 4; ++i) {
            int e = t + i * 256;
            int row = e >> 3, part = e & 7;
            uint4 v = *(const uint4*)((const char*)Es + row * 144 + part * 16);
            *(uint4*)((char*)g_ET + ((size_t)(j0 + row) * NPIX + p0) * 2 + part * 16) = v;
        }
        __syncthreads();
    }
    if (t < 64) g_srow[p0 + t] = rs2[t] + rs2[64 + t];
}

// ======== K2b: A'[c][p] = x[c][p] / s_p  (bf16) ========
__global__ __launch_bounds__(256) void k2b_scaleA(const float* __restrict__ x) {
    int i = blockIdx.x * 256 + threadIdx.x;
    int p = i % NPIX;
    float v = x[i] * __frcp_rn(g_srow[p]);
    g_Ap[i] = __float2bfloat16(v);
}

// ================= K3: x6 logits = A' @ E  (bf16 mma, fp32 accum) =============
// grid (72, 2): CTA tile 128x128, K=9216 in chunks of 32.
// cp.async double-buffered staging (no reg round-trip), ldmatrix.x4 fragment
// loads (12 LDSM vs 48 LDS.32 per thread/chunk), 2 CTAs/SM via launch_bounds.
// Pitch 40 elems (80B): 8-row x 16B ldmatrix phases hit all 32 banks (20r mod 32).
#define K3P 40   // smem pitch in bf16 elems (80 bytes)
__global__ __launch_bounds__(256, 2) void k3_gemm2() {
    __shared__ __align__(128) __nv_bfloat16 As[2][128 * K3P];
    __shared__ __align__(128) __nv_bfloat16 Bsm[2][128 * K3P];
    int t = threadIdx.x, lane = t & 31, wid = t >> 5;
    int mw = wid & 3, nw = wid >> 2;
    int m0 = blockIdx.y * 128;
    int j0 = blockIdx.x * 128;

    float acc[2][8][4];
#pragma unroll
    for (int mt = 0; mt < 2; ++mt)
#pragma unroll
        for (int nt = 0; nt < 8; ++nt)
            acc[mt][nt][0] = acc[mt][nt][1] = acc[mt][nt][2] = acc[mt][nt][3] = 0.f;

    // ---- staging coords: thread covers rows (t>>2) and (t>>2)+64, 16B each ----
    int srow = t >> 2, part = t & 3;
    const char* gA = (const char*)g_Ap + ((size_t)(m0 + srow) * NPIX) * 2 + part * 16;
    const char* gB = (const char*)g_ET + ((size_t)(j0 + srow) * NPIX) * 2 + part * 16;
    const size_t rstep = (size_t)64 * NPIX * 2;   // +64 rows in gmem

    unsigned sa[2] = { su32(As[0]),  su32(As[1])  };
    unsigned sb[2] = { su32(Bsm[0]), su32(Bsm[1]) };
    unsigned dstA = (unsigned)(srow * (K3P * 2) + part * 16);
    unsigned dstB = dstA;

    auto stage = [&](int buf, int kc) {
        size_t koff = (size_t)kc * 64;            // 32 bf16 = 64 bytes per chunk
        CP16(sa[buf] + dstA,                gA + koff);
        CP16(sa[buf] + dstA + 64 * (K3P*2), gA + rstep + koff);
        CP16(sb[buf] + dstB,                gB + koff);
        CP16(sb[buf] + dstB + 64 * (K3P*2), gB + rstep + koff);
        CP_COMMIT();
    };

    // ---- ldmatrix per-lane fragment addresses (quad = matrix index) ----
    int lrow = lane & 7, quad = lane >> 3;
    // A x4: m0=(rows ml..+7,k0-7) m1=(+8,k0-7) m2=(..,k8-15) m3=(+8,k8-15)
    unsigned aoff = (unsigned)((mw * 32 + lrow + (quad & 1) * 8) * (K3P * 2)
                               + (quad >> 1) * 16);
    // B x4: m0=(nt0 rows,k0-7) m1=(nt0,k8-15) m2=(nt1,k0-7) m3=(nt1,k8-15)
    unsigned boff = (unsigned)((nw * 64 + lrow + (quad >> 1) * 8) * (K3P * 2)
                               + (quad & 1) * 16);

    // ---- prologue: chunks 0,1 in flight ----
    stage(0, 0);
    stage(1, 1);
    CP_WAIT1();
    __syncthreads();

    const int NK = NPIX / 32;   // 288
    for (int kc = 0; kc < NK; ++kc) {
        int cur = kc & 1;
        unsigned baseA = sa[cur], baseB = sb[cur];
#pragma unroll
        for (int kf = 0; kf < 2; ++kf) {
            unsigned af[2][4], bfm[4][4];
#pragma unroll
            for (int mt = 0; mt < 2; ++mt)
                ldsm4(af[mt][0], af[mt][1], af[mt][2], af[mt][3],
                      baseA + aoff + mt * (16 * K3P * 2) + kf * 32);
#pragma unroll
            for (int p = 0; p < 4; ++p)
                ldsm4(bfm[p][0], bfm[p][1], bfm[p][2], bfm[p][3],
                      baseB + boff + p * (16 * K3P * 2) + kf * 32);
#pragma unroll
            for (int nt = 0; nt < 8; ++nt) {
                unsigned b0 = bfm[nt >> 1][(nt & 1) * 2];
                unsigned b1 = bfm[nt >> 1][(nt & 1) * 2 + 1];
                mma_bf16_16816(acc[0][nt], af[0], b0, b1);
                mma_bf16_16816(acc[1][nt], af[1], b0, b1);
            }
        }
        __syncthreads();                 // all warps done reading buf[cur]
        if (kc + 2 < NK) {
            stage(cur, kc + 2);          // refill the buffer just consumed
            CP_WAIT1();                  // chunk kc+1 complete
        } else {
            CP_WAIT0();                  // drain tail
        }
        __syncthreads();                 // buf[cur^1] visible to all
    }
    // epilogue: fp32 logits
#pragma unroll
    for (int mt = 0; mt < 2; ++mt) {
        int m = m0 + mw * 32 + mt * 16 + (lane >> 2);
#pragma unroll
        for (int nt = 0; nt < 8; ++nt) {
            int j = j0 + nw * 64 + nt * 8 + ((lane & 3) << 1);
            *(float2*)&g_x6[(size_t)m * NPIX + j]       = make_float2(acc[mt][nt][0], acc[mt][nt][1]);
            *(float2*)&g_x6[(size_t)(m + 8) * NPIX + j] = make_float2(acc[mt][nt][2], acc[mt][nt][3]);
        }
    }
}

// ======== K4: per-row (c) max & sumexp of x6 logits ========
__global__ __launch_bounds__(256) void k4_rowstats() {
    __shared__ float sm[256];
    int c = blockIdx.x, t = threadIdx.x;
    const float* row = g_x6 + (size_t)c * NPIX;
    float m = -3.0e38f;
    for (int i = t; i < NPIX; i += 256) m = fmaxf(m, row[i]);
    sm[t] = m;
    __syncthreads();
    for (int s = 128; s > 0; s >>= 1) {
        if (t < s) sm[t] = fmaxf(sm[t], sm[t + s]);
        __syncthreads();
    }
    m = sm[0];
    __syncthreads();
    float acc = 0.f;
    for (int i = t; i < NPIX; i += 256) acc += __expf(row[i] - m);
    sm[t] = acc;
    __syncthreads();
    for (int s = 128; s > 0; s >>= 1) {
        if (t < s) sm[t] += sm[t + s];
        __syncthreads();
    }
    if (t == 0) { g_m6[c] = m; g_s6[c] = sm[0]; }
}

// ======== K5: out = softmax_w( softmax(x6)[c,h*96+w] + x[c,h,w] ) ========
// one warp per (c,h) row of 96; grid 3072 x 256
__global__ __launch_bounds__(256) void k5_final(const float* __restrict__ x,
                                                float* __restrict__ out) {
    int gw   = blockIdx.x * 8 + (threadIdx.x >> 5);
    int lane = threadIdx.x & 31;
    int c = gw / HW, h = gw % HW;
    float m6  = g_m6[c];
    float is6 = __frcp_rn(g_s6[c]);
    float v[3];
    size_t base = (size_t)c * NPIX + h * HW;
#pragma unroll
    for (int k = 0; k < 3; ++k) {
        size_t idx = base + lane + 32 * k;
        float x6 = __expf(g_x6[idx] - m6) * is6;
        v[k] = x6 + x[idx];
    }
    float mx = fmaxf(fmaxf(v[0], v[1]), v[2]);
#pragma unroll
    for (int o = 16; o > 0; o >>= 1) mx = fmaxf(mx, __shfl_xor_sync(0xffffffffu, mx, o));
    float e[3];
    float s = 0.f;
#pragma unroll
    for (int k = 0; k < 3; ++k) { e[k] = __expf(v[k] - mx); s += e[k]; }
#pragma unroll
    for (int o = 16; o > 0; o >>= 1) s += __shfl_xor_sync(0xffffffffu, s, o);
    float is = __frcp_rn(s);
#pragma unroll
    for (int k = 0; k < 3; ++k) out[base + lane + 32 * k] = e[k] * is;
}

// =============================== launch ======================================
extern "C" void kernel_launch(void* const* d_in, const int* in_sizes, int n_in,
                              void* d_out, int out_size) {
    const float* x = nullptr; const float* w = nullptr; const float* b = nullptr;
    for (int i = 0; i < n_in; ++i) {
        if      (in_sizes[i] == CIN * NPIX) x = (const float*)d_in[i];
        else if (in_sizes[i] == C8 * CIN)   w = (const float*)d_in[i];
        else if (in_sizes[i] == C8)         b = (const float*)d_in[i];
    }
    float* out = (float*)d_out;

    k1_conv   <<<NPIX / 32, 256>>>(x, w, b);
    k2_attn1  <<<NPIX / 64, 256>>>();
    k2b_scaleA<<<(CIN * NPIX) / 256, 256>>>(x);
    k3_gemm2  <<<dim3(NPIX / 128, CIN / 128), 256>>>();
    k4_rowstats<<<CIN, 256>>>();
    k5_final  <<<(CIN * HW) / 8, 256>>>(x, out);
}